// round 16
// baseline (speedup 1.0000x reference)
#include <cuda_runtime.h>
#include <math.h>
#include <stdint.h>

#define NN 3000
#define NFEATD 512
#define AA 2
#define HHD 4
#define O1D 64
#define O2D 32
#define HO1D 256
#define HO2D 128
#define LDW1 512          // flattened gat1 row width
#define LDW2 256          // flattened gat2 row width
#define FUSD 64
#define NCLSD 8
#define WPR 94
#define NT64 47           // ceil(3000/64) 64-m stages
#define MPPAD 1504        // NT64*32 padded mp rows
#define ALPHAF 0.2f

// ---------------- scratch ----------------
__device__ float g_gat1[NN*LDW1];
__device__ float g_gat2[NN*LDW2];
__device__ uint32_t g_WhB[8*MPPAD*O1D]; // bf16x2-packed Wh pairs [z][mp][o]
__device__ float g_f1[AA*HHD*NN], g_ea[AA*HHD*NN], g_eb[AA*HHD*NN];
__device__ float4 g_mfac4[AA*HHD*NN];   // (f2, exp(f2), exp(a*f2), 0)
__device__ unsigned g_bits[AA*WPR*NN];  // [a][mt32][n]
__device__ float g_h1p[NN*AA*FUSD];
__device__ float g_out1[NN*FUSD];

// ---------------- mma / async helpers ----------------
__device__ __forceinline__ void mma_bf16(float* c, uint32_t a0, uint32_t a1,
                                         uint32_t a2, uint32_t a3,
                                         uint32_t b0, uint32_t b1) {
    asm volatile(
        "mma.sync.aligned.m16n8k16.row.col.f32.bf16.bf16.f32 "
        "{%0,%1,%2,%3}, {%4,%5,%6,%7}, {%8,%9}, {%0,%1,%2,%3};\n"
        : "+f"(c[0]), "+f"(c[1]), "+f"(c[2]), "+f"(c[3])
        : "r"(a0), "r"(a1), "r"(a2), "r"(a3), "r"(b0), "r"(b1));
}
__device__ __forceinline__ uint32_t pack_bf16x2(float hi, float lo) {
    uint32_t r;
    asm("cvt.rn.bf16x2.f32 %0, %1, %2;" : "=r"(r) : "f"(hi), "f"(lo));
    return r;
}
__device__ __forceinline__ void cp_async16(uint32_t dst_smem, const void* src) {
    asm volatile("cp.async.cg.shared.global [%0], [%1], 16;" :: "r"(dst_smem), "l"(src));
}
__device__ __forceinline__ void cp_async_commit() {
    asm volatile("cp.async.commit_group;");
}
__device__ __forceinline__ void cp_async_wait0() {
    asm volatile("cp.async.wait_group 0;");
}
__device__ __forceinline__ void cp_async_wait1() {
    asm volatile("cp.async.wait_group 1;");
}

// ---------------- adjacency -> bitmask via ballot ----------------
__global__ void bitmask_kernel(const int* __restrict__ adj) {
    int gw = (blockIdx.x * blockDim.x + threadIdx.x) >> 5;
    int lane = threadIdx.x & 31;
    if (gw >= AA * NN * WPR) return;
    int a = gw / (NN * WPR);
    int rem = gw % (NN * WPR);
    int n = rem / WPR;
    int mt = rem % WPR;
    int m = mt * 32 + lane;
    int v = 0;
    if (m < NN) v = adj[(size_t)(a * NN + n) * NN + m] > 0;
    unsigned word = __ballot_sync(0xffffffffu, v);
    if (lane == 0) g_bits[(size_t)(a * WPR + mt) * NN + n] = word;
}

// ---------------- Wh-stage bf16 GEMM with fused fprep + bf16 repack epilogue ----------------
template <int O>
__global__ void gemm_whprep_kernel(const float* __restrict__ A, const float* __restrict__ B,
                                   const float* __restrict__ avec,
                                   uint32_t* __restrict__ WhB,
                                   float* __restrict__ f1o, float* __restrict__ eao,
                                   float* __restrict__ ebo, float4* __restrict__ mfac,
                                   int M, int K, int lda, int ldb,
                                   long long sBh) {
    constexpr int BS = O + 8;           // uint32 row stride for Bs
    constexpr int NT = O / 16;
    int z = blockIdx.y;                 // = a*HHD + h
    B += (long long)z * sBh;
    const float* av = avec + (size_t)z * 2 * O;

    __shared__ uint32_t As[64][20];     // bf16x2 pairs along k (16 kp + pad)
    __shared__ uint32_t Bs[16][BS];
    __shared__ float f1s[64], f2s[64];

    int tid = threadIdx.x, w = tid >> 5, lane = tid & 31;
    int rg = w >> 1, cg = w & 1;
    int g = lane >> 2, t4 = lane & 3;
    int m0 = blockIdx.x * 64;

    if (tid < 64) { f1s[tid] = 0.f; f2s[tid] = 0.f; }

    float acc[NT][4];
#pragma unroll
    for (int i = 0; i < NT; i++)
#pragma unroll
        for (int j = 0; j < 4; j++) acc[i][j] = 0.f;

    for (int k0 = 0; k0 < K; k0 += 32) {
        __syncthreads();
#pragma unroll
        for (int i = 0; i < 4; i++) {
            int e = tid + i * 256;
            int r = e >> 4, kp = e & 15;
            int m = m0 + r;
            float2 v = (m < M) ? *(const float2*)&A[(size_t)m * lda + k0 + 2 * kp]
                               : make_float2(0.f, 0.f);
            As[r][kp] = pack_bf16x2(v.y, v.x);
        }
#pragma unroll
        for (int i = 0; i < (16 * O) / 256; i++) {
            int e = tid + i * 256;
            int kp, c;
            if (O == 64) { kp = e >> 6; c = e & 63; } else { kp = e >> 5; c = e & 31; }
            float lo = B[(size_t)(k0 + 2 * kp) * ldb + c];
            float hi = B[(size_t)(k0 + 2 * kp + 1) * ldb + c];
            Bs[kp][c] = pack_bf16x2(hi, lo);
        }
        __syncthreads();
#pragma unroll
        for (int kk = 0; kk < 2; kk++) {
            int kpb = kk * 8;
            int ar = rg * 16 + g;
            uint32_t a0 = As[ar][kpb + t4];
            uint32_t a1 = As[ar + 8][kpb + t4];
            uint32_t a2 = As[ar][kpb + t4 + 4];
            uint32_t a3 = As[ar + 8][kpb + t4 + 4];
#pragma unroll
            for (int nt = 0; nt < NT; nt++) {
                int col = cg * (O / 2) + nt * 8 + g;
                uint32_t b0 = Bs[kpb + t4][col];
                uint32_t b1 = Bs[kpb + t4 + 4][col];
                mma_bf16(acc[nt], a0, a1, a2, a3, b0, b1);
            }
        }
    }
    __syncthreads();

    // ---- fused epilogue: f1/f2 dot + bf16x2 pack (fp32 accumulators) ----
#pragma unroll
    for (int half = 0; half < 2; half++) {
        int r = rg * 16 + g + half * 8;
        int gr = m0 + r;
        float p1 = 0.f, p2 = 0.f;
#pragma unroll
        for (int nt = 0; nt < NT; nt++) {
            int col = cg * (O / 2) + nt * 8 + 2 * t4;
            float v0 = acc[nt][half * 2 + 0];
            float v1 = acc[nt][half * 2 + 1];
            p1 += v0 * av[col] + v1 * av[col + 1];
            p2 += v0 * av[O + col] + v1 * av[O + col + 1];
            float u0 = __shfl_xor_sync(0xffffffffu, v0, 4);
            float u1 = __shfl_xor_sync(0xffffffffu, v1, 4);
            if ((g & 1) == 0) {
                uint2 p;
                p.x = pack_bf16x2(u0, v0);
                p.y = pack_bf16x2(u1, v1);
                *(uint2*)&WhB[(size_t)z * MPPAD * O + (size_t)(gr >> 1) * O + col] = p;
            }
        }
        p1 += __shfl_xor_sync(0xffffffffu, p1, 1);
        p1 += __shfl_xor_sync(0xffffffffu, p1, 2);
        p2 += __shfl_xor_sync(0xffffffffu, p2, 1);
        p2 += __shfl_xor_sync(0xffffffffu, p2, 2);
        if (t4 == 0) {
            atomicAdd(&f1s[r], p1);
            atomicAdd(&f2s[r], p2);
        }
    }
    __syncthreads();
    if (tid < 64) {
        int gr = m0 + tid;
        if (gr < NN) {
            float f1 = f1s[tid], f2 = f2s[tid];
            size_t idx = (size_t)z * NN + gr;
            f1o[idx] = f1;
            eao[idx] = expf(f1);
            ebo[idx] = expf(ALPHAF * f1);
            mfac[idx] = make_float4(f2, expf(f2), expf(ALPHAF * f2), 0.f);
        }
    }
}

// ---------------- bf16 GEMM, B native [Ncols][K] layout, 32-row tiles ----------------
// C[m, c] = sum_k A[m,k] * BT[c,k] (+bias[c]) (elu if act); 64 cols.
__global__ void gemm_bt_kernel(const float* __restrict__ A, const float* __restrict__ BT,
                               float* __restrict__ C, const float* __restrict__ bias,
                               int M, int K, int lda, int sAh, int ldc, int cOffH, int act) {
    int zh = blockIdx.y;
    A += (size_t)zh * sAh;
    C += (size_t)zh * cOffH;

    __shared__ uint32_t As[32][20];
    __shared__ uint32_t Bs[16][72];

    int tid = threadIdx.x, w = tid >> 5, lane = tid & 31;
    int rg = w >> 2, cg = w & 3;        // 2 rowgroups x 4 colgroups (16 cols each)
    int g = lane >> 2, t4 = lane & 3;
    int m0 = blockIdx.x * 32;

    float acc[2][4];
#pragma unroll
    for (int i = 0; i < 2; i++)
#pragma unroll
        for (int j = 0; j < 4; j++) acc[i][j] = 0.f;

    for (int k0 = 0; k0 < K; k0 += 32) {
        __syncthreads();
#pragma unroll
        for (int i = 0; i < 2; i++) {
            int e = tid + i * 256;
            int r = e >> 4, kp = e & 15;
            int m = m0 + r;
            float2 v = (m < M) ? *(const float2*)&A[(size_t)m * lda + k0 + 2 * kp]
                               : make_float2(0.f, 0.f);
            As[r][kp] = pack_bf16x2(v.y, v.x);
        }
#pragma unroll
        for (int i = 0; i < 4; i++) {
            int e = tid + i * 256;
            int c = e >> 4, kp = e & 15;
            float2 v = *(const float2*)&BT[(size_t)c * K + k0 + 2 * kp];
            Bs[kp][c] = pack_bf16x2(v.y, v.x);
        }
        __syncthreads();
#pragma unroll
        for (int kk = 0; kk < 2; kk++) {
            int kpb = kk * 8;
            int ar = rg * 16 + g;
            uint32_t a0 = As[ar][kpb + t4];
            uint32_t a1 = As[ar + 8][kpb + t4];
            uint32_t a2 = As[ar][kpb + t4 + 4];
            uint32_t a3 = As[ar + 8][kpb + t4 + 4];
#pragma unroll
            for (int nt = 0; nt < 2; nt++) {
                int col = cg * 16 + nt * 8 + g;
                uint32_t b0 = Bs[kpb + t4][col];
                uint32_t b1 = Bs[kpb + t4 + 4][col];
                mma_bf16(acc[nt], a0, a1, a2, a3, b0, b1);
            }
        }
    }
#pragma unroll
    for (int half = 0; half < 2; half++) {
        int r = rg * 16 + g + half * 8;
        int gr = m0 + r;
        if (gr < M) {
#pragma unroll
            for (int nt = 0; nt < 2; nt++) {
                int col = cg * 16 + nt * 8 + 2 * t4;
                float v0 = acc[nt][half * 2 + 0];
                float v1 = acc[nt][half * 2 + 1];
                if (bias) { v0 += bias[col]; v1 += bias[col + 1]; }
                if (act == 1) {
                    v0 = v0 > 0.f ? v0 : (expf(v0) - 1.f);
                    v1 = v1 > 0.f ? v1 : (expf(v1) - 1.f);
                }
                *(float2*)&C[(size_t)gr * ldc + col] = make_float2(v0, v1);
            }
        }
    }
}

// ---------------- attention weight (raw fp32; rounded at pack) ----------------
__device__ __forceinline__ float attw_f(unsigned word, int mb, float f1n, float ean,
                                        float ebn, const float4 q) {
    float wv = 0.f;
    if ((word >> mb) & 1u) {
        float s = f1n + q.x;
        wv = (s > 0.f) ? ean * q.y : ebn * q.z;
    }
    return wv;
}

// ---------------- fused masked-softmax attention aggregate ----------------
// 64-row tiles; 8 warps = 4 rowgroups x 2 k-groups. 64-m stages, 3-buffer
// cp.async pipeline (wait_group 1 gives each copy a full iteration of slack).
template <int O>
__global__ void att_mma_kernel(const uint32_t* __restrict__ WhB,
                               const float* __restrict__ f1v, const float* __restrict__ eav,
                               const float* __restrict__ ebv,
                               const float4* __restrict__ mfac,
                               const unsigned* __restrict__ bits,
                               float* __restrict__ outp) {
    constexpr int LDW = AA * HHD * O;
    constexpr int NT = O / 8;
    constexpr int BSTRIDE = (O == 64) ? 72 : 40;
    constexpr int CPR = O / 4;
    int z = blockIdx.y;
    int a = z >> 2, h = z & 3;
    int n0 = blockIdx.x * 64;
    const uint32_t* wbb = WhB + (size_t)z * MPPAD * O;
    const float4* mfb = mfac + (size_t)z * NN;
    const unsigned* bb = bits + (size_t)a * WPR * NN;

    __shared__ uint32_t Whs[3][32 * BSTRIDE];    // mrg aliases this after main loop
    __shared__ float4 mfs[3][64];
    __shared__ unsigned wds[3][2][64];
    __shared__ float Zbuf[64];

    int tid = threadIdx.x, w = tid >> 5, lane = tid & 31;
    int rg = w >> 1, kg = w & 1;
    int g = lane >> 2, t4 = lane & 3;
    int r0 = rg * 16 + g, r1 = r0 + 8;
    int gr0 = n0 + r0, gr1 = n0 + r1;

    uint32_t whs0 = (uint32_t)__cvta_generic_to_shared(&Whs[0][0]);

    float f10 = 0.f, ea0 = 0.f, eb0 = 0.f, f11 = 0.f, ea1 = 0.f, eb1 = 0.f;
    if (gr0 < NN) { f10 = f1v[(size_t)z*NN+gr0]; ea0 = eav[(size_t)z*NN+gr0]; eb0 = ebv[(size_t)z*NN+gr0]; }
    if (gr1 < NN) { f11 = f1v[(size_t)z*NN+gr1]; ea1 = eav[(size_t)z*NN+gr1]; eb1 = ebv[(size_t)z*NN+gr1]; }

    float acc[NT][4];
#pragma unroll
    for (int i = 0; i < NT; i++)
#pragma unroll
        for (int j = 0; j < 4; j++) acc[i][j] = 0.f;
    float zp0 = 0.f, zp1 = 0.f;

    auto build = [&](int mt, int buf) {
#pragma unroll
        for (int i = 0; i < (32 * CPR) / 256; i++) {
            int c = tid + i * 256;
            int row = c / CPR;
            int col = (c % CPR) * 4;
            uint32_t dst = whs0 + (uint32_t)(buf * 32 * BSTRIDE + row * BSTRIDE + col) * 4u;
            cp_async16(dst, wbb + (size_t)(mt * 32 + row) * O + col);
        }
        if (tid < 64) {
            int m = mt * 64 + tid;
            mfs[buf][tid] = (m < NN) ? mfb[m] : make_float4(0.f, 0.f, 0.f, 0.f);
        } else if (tid < 192) {
            int j = (tid - 64) >> 6, n = (tid - 64) & 63;
            int rr = n0 + n;
            int wi = mt * 2 + j;
            wds[buf][j][n] = (rr < NN && wi < WPR) ? bb[(size_t)wi * NN + rr] : 0u;
        }
    };

    build(0, 0);
    cp_async_commit();
    build(1, 1);
    cp_async_commit();

    int kb = kg * 16;
    for (int mt = 0; mt < NT64; mt++) {
        if (mt + 1 < NT64) cp_async_wait1(); else cp_async_wait0();
        __syncthreads();
        int cur = mt % 3;
#pragma unroll
        for (int sub = 0; sub < 2; sub++) {
            unsigned w0 = wds[cur][sub][r0], w1 = wds[cur][sub][r1];
            int base = sub * 32 + kb;
            float4 qa = mfs[cur][base + 2 * t4];
            float4 qb = mfs[cur][base + 2 * t4 + 1];
            float4 qc = mfs[cur][base + 2 * t4 + 8];
            float4 qd = mfs[cur][base + 2 * t4 + 9];
            float w0a = attw_f(w0, kb + 2 * t4,     f10, ea0, eb0, qa);
            float w0b = attw_f(w0, kb + 2 * t4 + 1, f10, ea0, eb0, qb);
            float w0c = attw_f(w0, kb + 2 * t4 + 8, f10, ea0, eb0, qc);
            float w0d = attw_f(w0, kb + 2 * t4 + 9, f10, ea0, eb0, qd);
            float w1a = attw_f(w1, kb + 2 * t4,     f11, ea1, eb1, qa);
            float w1b = attw_f(w1, kb + 2 * t4 + 1, f11, ea1, eb1, qb);
            float w1c = attw_f(w1, kb + 2 * t4 + 8, f11, ea1, eb1, qc);
            float w1d = attw_f(w1, kb + 2 * t4 + 9, f11, ea1, eb1, qd);
            zp0 += (w0a + w0b) + (w0c + w0d);
            zp1 += (w1a + w1b) + (w1c + w1d);
            uint32_t a0 = pack_bf16x2(w0b, w0a);
            uint32_t a1 = pack_bf16x2(w1b, w1a);
            uint32_t a2 = pack_bf16x2(w0d, w0c);
            uint32_t a3 = pack_bf16x2(w1d, w1c);
            int row0 = sub * 16 + kg * 8 + t4, row1 = row0 + 4;
#pragma unroll
            for (int nt = 0; nt < NT; nt++) {
                int col = nt * 8 + g;
                uint32_t b0 = Whs[cur][row0 * BSTRIDE + col];
                uint32_t b1 = Whs[cur][row1 * BSTRIDE + col];
                mma_bf16(acc[nt], a0, a1, a2, a3, b0, b1);
            }
        }
        if (mt + 2 < NT64) { build(mt + 2, (mt + 2) % 3); cp_async_commit(); }
    }
    __syncthreads();   // Whs dead from here; safe to alias as mrg

#pragma unroll
    for (int d = 1; d < 4; d <<= 1) {
        zp0 += __shfl_xor_sync(0xffffffffu, zp0, d);
        zp1 += __shfl_xor_sync(0xffffffffu, zp1, d);
    }

    float* mrg = (float*)&Whs[0][0];
    int flat = rg * 32 + lane;
    if (kg == 1) {
#pragma unroll
        for (int nt = 0; nt < NT; nt++)
#pragma unroll
            for (int j = 0; j < 4; j++)
                mrg[(nt * 4 + j) * 128 + flat] = acc[nt][j];
        if (t4 == 0) { Zbuf[r0] = zp0; Zbuf[r1] = zp1; }
    }
    __syncthreads();
    if (kg == 0) {
#pragma unroll
        for (int nt = 0; nt < NT; nt++)
#pragma unroll
            for (int j = 0; j < 4; j++)
                acc[nt][j] += mrg[(nt * 4 + j) * 128 + flat];
        zp0 += Zbuf[r0];
        zp1 += Zbuf[r1];
        float inv0 = (zp0 > 0.f) ? 1.f / zp0 : 0.f;
        float inv1 = (zp1 > 0.f) ? 1.f / zp1 : 0.f;
#pragma unroll
        for (int nt = 0; nt < NT; nt++) {
            int col = nt * 8 + 2 * t4;
            if (gr0 < NN) {
                float v0 = acc[nt][0] * inv0;
                float v1 = acc[nt][1] * inv0;
                v0 = v0 > 0.f ? v0 : (expf(v0) - 1.f);
                v1 = v1 > 0.f ? v1 : (expf(v1) - 1.f);
                *(float2*)&outp[(size_t)gr0 * LDW + (a * HHD + h) * O + col] = make_float2(v0, v1);
            }
            if (gr1 < NN) {
                float v2 = acc[nt][2] * inv1;
                float v3 = acc[nt][3] * inv1;
                v2 = v2 > 0.f ? v2 : (expf(v2) - 1.f);
                v3 = v3 > 0.f ? v3 : (expf(v3) - 1.f);
                *(float2*)&outp[(size_t)gr1 * LDW + (a * HHD + h) * O + col] = make_float2(v2, v3);
            }
        }
    }
}

// ---------------- fused interproj2 + fusion2 + log_softmax ----------------
__global__ void ipfus2_kernel(const float* __restrict__ gat2,
                              const float* __restrict__ wint2,
                              const float* __restrict__ bint2,
                              const float* __restrict__ wfus2,
                              const float* __restrict__ bfus2,
                              float* __restrict__ out, int out_size) {
    __shared__ float w2s[HO2D][9];
    __shared__ float wf2s[16][9];
    __shared__ float b2s[8], bf2s[8];
    __shared__ float h2ps[64][17];
    __shared__ float lg[64][9];

    int tid = threadIdx.x;
#pragma unroll
    for (int i = 0; i < 4; i++) {
        int e = tid + i * 256;
        if (e < HO2D * NCLSD) {
            int k = e & 127, c = e >> 7;
            w2s[k][c] = wint2[c * HO2D + k];
        }
    }
    if (tid < 16 * NCLSD) {
        int ee = tid & 15, c = tid >> 4;
        wf2s[ee][c] = wfus2[c * (AA * NCLSD) + ee];
    }
    if (tid < 8) { b2s[tid] = bint2[tid]; bf2s[tid] = bfus2[tid]; }
    __syncthreads();

    int r = tid >> 2, t4 = tid & 3;
    int row = blockIdx.x * 64 + r;
    int a = t4 >> 1, cb = (t4 & 1) * 4;
    if (row < NN) {
        float acc[4] = {0.f, 0.f, 0.f, 0.f};
        const float* gr = gat2 + (size_t)row * LDW2 + a * HO2D;
        for (int k = 0; k < HO2D; k += 4) {
            float4 gv = *(const float4*)(gr + k);
#pragma unroll
            for (int j = 0; j < 4; j++) {
                acc[j] += gv.x * w2s[k][cb + j] + gv.y * w2s[k + 1][cb + j]
                        + gv.z * w2s[k + 2][cb + j] + gv.w * w2s[k + 3][cb + j];
            }
        }
#pragma unroll
        for (int j = 0; j < 4; j++) {
            float v = acc[j] + b2s[cb + j];
            v = v > 0.f ? v : (expf(v) - 1.f);
            h2ps[r][t4 * 4 + j] = v;
        }
    }
    __syncwarp();
    if (row < NN) {
#pragma unroll
        for (int ci = 0; ci < 2; ci++) {
            int c = t4 * 2 + ci;
            float lv = bf2s[c];
#pragma unroll
            for (int e = 0; e < 16; e++) lv += h2ps[r][e] * wf2s[e][c];
            lg[r][c] = lv;
        }
    }
    __syncwarp();
    if (row < NN && t4 == 0) {
        float mx = -1e30f;
#pragma unroll
        for (int c = 0; c < 8; c++) mx = fmaxf(mx, lg[r][c]);
        float s = 0.f;
#pragma unroll
        for (int c = 0; c < 8; c++) s += expf(lg[r][c] - mx);
        float l = logf(s) + mx;
#pragma unroll
        for (int c = 0; c < 8; c++) {
            int idx = row * NCLSD + c;
            if (idx < out_size) out[idx] = lg[r][c] - l;
        }
    }
}

// ---------------- L1 scalar ----------------
__global__ void l1_kernel(const float* __restrict__ wfus1, const float* __restrict__ wfus2,
                          float* __restrict__ out, int out_size) {
    __shared__ float red[256];
    int tid = threadIdx.x;
    float s1 = 0.f, s2 = 0.f;
    for (int i = tid; i < FUSD * AA * FUSD; i += 256) s1 += fabsf(wfus1[i]);
    for (int i = tid; i < NCLSD * AA * NCLSD; i += 256) s2 += fabsf(wfus2[i]);
    red[tid] = s1 / (float)(FUSD * AA * FUSD) + s2 / (float)(NCLSD * AA * NCLSD);
    __syncthreads();
    for (int o = 128; o > 0; o >>= 1) {
        if (tid < o) red[tid] += red[tid + o];
        __syncthreads();
    }
    if (tid == 0 && out_size > NN * NCLSD) out[NN * NCLSD] = red[0];
}

// ---------------- host launcher ----------------
extern "C" void kernel_launch(void* const* d_in, const int* in_sizes, int n_in,
                              void* d_out, int out_size) {
    const float* x     = (const float*)d_in[0];
    const int*   adj   = (const int*)d_in[1];
    const float* W1    = (const float*)d_in[2];
    const float* a1    = (const float*)d_in[3];
    const float* W2    = (const float*)d_in[4];
    const float* a2    = (const float*)d_in[5];
    const float* wint1 = (const float*)d_in[6];
    const float* bint1 = (const float*)d_in[7];
    const float* wfus1 = (const float*)d_in[8];
    const float* bfus1 = (const float*)d_in[9];
    const float* wint2 = (const float*)d_in[10];
    const float* bint2 = (const float*)d_in[11];
    const float* wfus2 = (const float*)d_in[12];
    const float* bfus2 = (const float*)d_in[13];
    float* out = (float*)d_out;

    float *pgat1, *pgat2;
    float *pf1, *pea, *peb;
    float4* pmfac;
    uint32_t* pWhB;
    float *ph1p, *pout1;
    unsigned* pbits;
    cudaGetSymbolAddress((void**)&pgat1, g_gat1);
    cudaGetSymbolAddress((void**)&pgat2, g_gat2);
    cudaGetSymbolAddress((void**)&pf1, g_f1);
    cudaGetSymbolAddress((void**)&pea, g_ea);
    cudaGetSymbolAddress((void**)&peb, g_eb);
    cudaGetSymbolAddress((void**)&pmfac, g_mfac4);
    cudaGetSymbolAddress((void**)&pWhB, g_WhB);
    cudaGetSymbolAddress((void**)&pbits, g_bits);
    cudaGetSymbolAddress((void**)&ph1p, g_h1p);
    cudaGetSymbolAddress((void**)&pout1, g_out1);

    int nblk64 = (NN + 63) / 64;     // 47
    int nblk32 = (NN + 31) / 32;     // 94

    // adjacency bitmask
    {
        long long warps = (long long)AA * NN * WPR;
        int blocks = (int)((warps * 32 + 255) / 256);
        bitmask_kernel<<<blocks, 256>>>(adj);
    }

    // stage 1: Wh1 bf16 GEMM with fused fprep + bf16 repack
    gemm_whprep_kernel<O1D><<<dim3(nblk64, AA * HHD), 256>>>(
        x, W1, a1, pWhB, pf1, pea, peb, pmfac,
        NN, NFEATD, NFEATD, O1D, (long long)NFEATD * O1D);

    // att1
    att_mma_kernel<O1D><<<dim3(nblk64, AA * HHD), 256>>>(
        pWhB, pf1, pea, peb, pmfac, pbits, pgat1);

    // interproj1: elu(gat1[:, a*256:(a+1)*256] @ wint1^T + bint1) -> h1p[n][a*64+g]
    gemm_bt_kernel<<<dim3(nblk32, AA), 256>>>(
        pgat1, wint1, ph1p, bint1, NN, HO1D, LDW1, HO1D, AA * FUSD, FUSD, 1);

    // fusion1: out1 = h1p @ wfus1^T + bfus1
    gemm_bt_kernel<<<dim3(nblk32, 1), 256>>>(
        ph1p, wfus1, pout1, bfus1, NN, AA * FUSD, AA * FUSD, 0, FUSD, 0, 0);

    // stage 2: Wh2 bf16 GEMM with fused fprep + repack
    gemm_whprep_kernel<O2D><<<dim3(nblk64, AA * HHD), 256>>>(
        pout1, W2, a2, pWhB, pf1, pea, peb, pmfac,
        NN, FUSD, FUSD, O2D, (long long)FUSD * O2D);

    att_mma_kernel<O2D><<<dim3(nblk64, AA * HHD), 256>>>(
        pWhB, pf1, pea, peb, pmfac, pbits, pgat2);

    // fused interproj2 + fusion2 + log_softmax -> out
    ipfus2_kernel<<<nblk64, 256>>>(pgat2, wint2, bint2, wfus2, bfus2, out, out_size);

    l1_kernel<<<1, 256>>>(wfus1, wfus2, out, out_size);
}

// round 17
// speedup vs baseline: 1.0257x; 1.0257x over previous
#include <cuda_runtime.h>
#include <math.h>
#include <stdint.h>

#define NN 3000
#define NFEATD 512
#define AA 2
#define HHD 4
#define O1D 64
#define O2D 32
#define HO1D 256
#define HO2D 128
#define LDW1 512          // flattened gat1 row width
#define LDW2 256          // flattened gat2 row width
#define FUSD 64
#define NCLSD 8
#define WPR 94
#define NT64 47           // ceil(3000/64) 64-m stages
#define MPPAD 1504        // NT64*32 padded mp rows
#define ALPHAF 0.2f

// ---------------- scratch ----------------
__device__ float g_gat1[NN*LDW1];
__device__ float g_gat2[NN*LDW2];
__device__ uint32_t g_WhB[8*MPPAD*O1D]; // bf16x2-packed Wh pairs [z][mp][o]
__device__ float g_f1[AA*HHD*NN], g_ea[AA*HHD*NN], g_eb[AA*HHD*NN];
__device__ float4 g_mfac4[AA*HHD*NN];   // (f2, exp(f2), exp(a*f2), 0)
__device__ unsigned g_bits[AA*WPR*NN];  // [a][mt32][n]
__device__ float g_h1p[NN*AA*FUSD];
__device__ float g_out1[NN*FUSD];

// ---------------- mma / async helpers ----------------
__device__ __forceinline__ void mma_bf16(float* c, uint32_t a0, uint32_t a1,
                                         uint32_t a2, uint32_t a3,
                                         uint32_t b0, uint32_t b1) {
    asm volatile(
        "mma.sync.aligned.m16n8k16.row.col.f32.bf16.bf16.f32 "
        "{%0,%1,%2,%3}, {%4,%5,%6,%7}, {%8,%9}, {%0,%1,%2,%3};\n"
        : "+f"(c[0]), "+f"(c[1]), "+f"(c[2]), "+f"(c[3])
        : "r"(a0), "r"(a1), "r"(a2), "r"(a3), "r"(b0), "r"(b1));
}
__device__ __forceinline__ uint32_t pack_bf16x2(float hi, float lo) {
    uint32_t r;
    asm("cvt.rn.bf16x2.f32 %0, %1, %2;" : "=r"(r) : "f"(hi), "f"(lo));
    return r;
}
__device__ __forceinline__ void cp_async16(uint32_t dst_smem, const void* src) {
    asm volatile("cp.async.cg.shared.global [%0], [%1], 16;" :: "r"(dst_smem), "l"(src));
}
__device__ __forceinline__ void cp_async_commit() {
    asm volatile("cp.async.commit_group;");
}
__device__ __forceinline__ void cp_async_wait0() {
    asm volatile("cp.async.wait_group 0;");
}

// ---------------- adjacency -> bitmask via ballot ----------------
__global__ void bitmask_kernel(const int* __restrict__ adj) {
    int gw = (blockIdx.x * blockDim.x + threadIdx.x) >> 5;
    int lane = threadIdx.x & 31;
    if (gw >= AA * NN * WPR) return;
    int a = gw / (NN * WPR);
    int rem = gw % (NN * WPR);
    int n = rem / WPR;
    int mt = rem % WPR;
    int m = mt * 32 + lane;
    int v = 0;
    if (m < NN) v = adj[(size_t)(a * NN + n) * NN + m] > 0;
    unsigned word = __ballot_sync(0xffffffffu, v);
    if (lane == 0) g_bits[(size_t)(a * WPR + mt) * NN + n] = word;
}

// ---------------- Wh-stage bf16 GEMM with fused fprep + bf16 repack epilogue ----------------
template <int O>
__global__ void gemm_whprep_kernel(const float* __restrict__ A, const float* __restrict__ B,
                                   const float* __restrict__ avec,
                                   uint32_t* __restrict__ WhB,
                                   float* __restrict__ f1o, float* __restrict__ eao,
                                   float* __restrict__ ebo, float4* __restrict__ mfac,
                                   int M, int K, int lda, int ldb,
                                   long long sBh) {
    constexpr int BS = O + 8;           // uint32 row stride for Bs
    constexpr int NT = O / 16;
    int z = blockIdx.y;                 // = a*HHD + h
    B += (long long)z * sBh;
    const float* av = avec + (size_t)z * 2 * O;

    __shared__ uint32_t As[64][20];     // bf16x2 pairs along k (16 kp + pad)
    __shared__ uint32_t Bs[16][BS];
    __shared__ float f1s[64], f2s[64];

    int tid = threadIdx.x, w = tid >> 5, lane = tid & 31;
    int rg = w >> 1, cg = w & 1;
    int g = lane >> 2, t4 = lane & 3;
    int m0 = blockIdx.x * 64;

    if (tid < 64) { f1s[tid] = 0.f; f2s[tid] = 0.f; }

    float acc[NT][4];
#pragma unroll
    for (int i = 0; i < NT; i++)
#pragma unroll
        for (int j = 0; j < 4; j++) acc[i][j] = 0.f;

    for (int k0 = 0; k0 < K; k0 += 32) {
        __syncthreads();
#pragma unroll
        for (int i = 0; i < 4; i++) {
            int e = tid + i * 256;
            int r = e >> 4, kp = e & 15;
            int m = m0 + r;
            float2 v = (m < M) ? *(const float2*)&A[(size_t)m * lda + k0 + 2 * kp]
                               : make_float2(0.f, 0.f);
            As[r][kp] = pack_bf16x2(v.y, v.x);
        }
#pragma unroll
        for (int i = 0; i < (16 * O) / 256; i++) {
            int e = tid + i * 256;
            int kp, c;
            if (O == 64) { kp = e >> 6; c = e & 63; } else { kp = e >> 5; c = e & 31; }
            float lo = B[(size_t)(k0 + 2 * kp) * ldb + c];
            float hi = B[(size_t)(k0 + 2 * kp + 1) * ldb + c];
            Bs[kp][c] = pack_bf16x2(hi, lo);
        }
        __syncthreads();
#pragma unroll
        for (int kk = 0; kk < 2; kk++) {
            int kpb = kk * 8;
            int ar = rg * 16 + g;
            uint32_t a0 = As[ar][kpb + t4];
            uint32_t a1 = As[ar + 8][kpb + t4];
            uint32_t a2 = As[ar][kpb + t4 + 4];
            uint32_t a3 = As[ar + 8][kpb + t4 + 4];
#pragma unroll
            for (int nt = 0; nt < NT; nt++) {
                int col = cg * (O / 2) + nt * 8 + g;
                uint32_t b0 = Bs[kpb + t4][col];
                uint32_t b1 = Bs[kpb + t4 + 4][col];
                mma_bf16(acc[nt], a0, a1, a2, a3, b0, b1);
            }
        }
    }
    __syncthreads();

    // ---- fused epilogue: f1/f2 dot + bf16x2 pack (fp32 accumulators) ----
#pragma unroll
    for (int half = 0; half < 2; half++) {
        int r = rg * 16 + g + half * 8;
        int gr = m0 + r;
        float p1 = 0.f, p2 = 0.f;
#pragma unroll
        for (int nt = 0; nt < NT; nt++) {
            int col = cg * (O / 2) + nt * 8 + 2 * t4;
            float v0 = acc[nt][half * 2 + 0];
            float v1 = acc[nt][half * 2 + 1];
            p1 += v0 * av[col] + v1 * av[col + 1];
            p2 += v0 * av[O + col] + v1 * av[O + col + 1];
            float u0 = __shfl_xor_sync(0xffffffffu, v0, 4);
            float u1 = __shfl_xor_sync(0xffffffffu, v1, 4);
            if ((g & 1) == 0) {
                uint2 p;
                p.x = pack_bf16x2(u0, v0);
                p.y = pack_bf16x2(u1, v1);
                *(uint2*)&WhB[(size_t)z * MPPAD * O + (size_t)(gr >> 1) * O + col] = p;
            }
        }
        p1 += __shfl_xor_sync(0xffffffffu, p1, 1);
        p1 += __shfl_xor_sync(0xffffffffu, p1, 2);
        p2 += __shfl_xor_sync(0xffffffffu, p2, 1);
        p2 += __shfl_xor_sync(0xffffffffu, p2, 2);
        if (t4 == 0) {
            atomicAdd(&f1s[r], p1);
            atomicAdd(&f2s[r], p2);
        }
    }
    __syncthreads();
    if (tid < 64) {
        int gr = m0 + tid;
        if (gr < NN) {
            float f1 = f1s[tid], f2 = f2s[tid];
            size_t idx = (size_t)z * NN + gr;
            f1o[idx] = f1;
            eao[idx] = expf(f1);
            ebo[idx] = expf(ALPHAF * f1);
            mfac[idx] = make_float4(f2, expf(f2), expf(ALPHAF * f2), 0.f);
        }
    }
}

// ---------------- bf16 GEMM, B native [Ncols][K] layout, 32-row tiles ----------------
// C[m, c] = sum_k A[m,k] * BT[c,k] (+bias[c]) (elu if act); 64 cols.
__global__ void gemm_bt_kernel(const float* __restrict__ A, const float* __restrict__ BT,
                               float* __restrict__ C, const float* __restrict__ bias,
                               int M, int K, int lda, int sAh, int ldc, int cOffH, int act) {
    int zh = blockIdx.y;
    A += (size_t)zh * sAh;
    C += (size_t)zh * cOffH;

    __shared__ uint32_t As[32][20];
    __shared__ uint32_t Bs[16][72];

    int tid = threadIdx.x, w = tid >> 5, lane = tid & 31;
    int rg = w >> 2, cg = w & 3;        // 2 rowgroups x 4 colgroups (16 cols each)
    int g = lane >> 2, t4 = lane & 3;
    int m0 = blockIdx.x * 32;

    float acc[2][4];
#pragma unroll
    for (int i = 0; i < 2; i++)
#pragma unroll
        for (int j = 0; j < 4; j++) acc[i][j] = 0.f;

    for (int k0 = 0; k0 < K; k0 += 32) {
        __syncthreads();
#pragma unroll
        for (int i = 0; i < 2; i++) {
            int e = tid + i * 256;
            int r = e >> 4, kp = e & 15;
            int m = m0 + r;
            float2 v = (m < M) ? *(const float2*)&A[(size_t)m * lda + k0 + 2 * kp]
                               : make_float2(0.f, 0.f);
            As[r][kp] = pack_bf16x2(v.y, v.x);
        }
#pragma unroll
        for (int i = 0; i < 4; i++) {
            int e = tid + i * 256;
            int c = e >> 4, kp = e & 15;
            float2 v = *(const float2*)&BT[(size_t)c * K + k0 + 2 * kp];
            Bs[kp][c] = pack_bf16x2(v.y, v.x);
        }
        __syncthreads();
#pragma unroll
        for (int kk = 0; kk < 2; kk++) {
            int kpb = kk * 8;
            int ar = rg * 16 + g;
            uint32_t a0 = As[ar][kpb + t4];
            uint32_t a1 = As[ar + 8][kpb + t4];
            uint32_t a2 = As[ar][kpb + t4 + 4];
            uint32_t a3 = As[ar + 8][kpb + t4 + 4];
#pragma unroll
            for (int nt = 0; nt < 2; nt++) {
                int col = cg * 16 + nt * 8 + g;
                uint32_t b0 = Bs[kpb + t4][col];
                uint32_t b1 = Bs[kpb + t4 + 4][col];
                mma_bf16(acc[nt], a0, a1, a2, a3, b0, b1);
            }
        }
    }
#pragma unroll
    for (int half = 0; half < 2; half++) {
        int r = rg * 16 + g + half * 8;
        int gr = m0 + r;
        if (gr < M) {
#pragma unroll
            for (int nt = 0; nt < 2; nt++) {
                int col = cg * 16 + nt * 8 + 2 * t4;
                float v0 = acc[nt][half * 2 + 0];
                float v1 = acc[nt][half * 2 + 1];
                if (bias) { v0 += bias[col]; v1 += bias[col + 1]; }
                if (act == 1) {
                    v0 = v0 > 0.f ? v0 : (expf(v0) - 1.f);
                    v1 = v1 > 0.f ? v1 : (expf(v1) - 1.f);
                }
                *(float2*)&C[(size_t)gr * ldc + col] = make_float2(v0, v1);
            }
        }
    }
}

// ---------------- attention weight (raw fp32; rounded at pack) ----------------
__device__ __forceinline__ float attw_f(unsigned word, int mb, float f1n, float ean,
                                        float ebn, const float4 q) {
    float wv = 0.f;
    if ((word >> mb) & 1u) {
        float s = f1n + q.x;
        wv = (s > 0.f) ? ean * q.y : ebn * q.z;
    }
    return wv;
}

// ---------------- fused masked-softmax attention aggregate (bf16 MMA + cp.async) --------
// 64-row tiles; 8 warps = 4 rowgroups x 2 k-groups. 64-m stages, double-buffered (R15).
template <int O>
__global__ void att_mma_kernel(const uint32_t* __restrict__ WhB,
                               const float* __restrict__ f1v, const float* __restrict__ eav,
                               const float* __restrict__ ebv,
                               const float4* __restrict__ mfac,
                               const unsigned* __restrict__ bits,
                               float* __restrict__ outp) {
    constexpr int LDW = AA * HHD * O;
    constexpr int NT = O / 8;
    constexpr int BSTRIDE = (O == 64) ? 72 : 40;
    constexpr int CPR = O / 4;
    int z = blockIdx.y;
    int a = z >> 2, h = z & 3;
    int n0 = blockIdx.x * 64;
    const uint32_t* wbb = WhB + (size_t)z * MPPAD * O;
    const float4* mfb = mfac + (size_t)z * NN;
    const unsigned* bb = bits + (size_t)a * WPR * NN;

    __shared__ uint32_t Whs[2][32 * BSTRIDE];
    __shared__ float4 mfs[2][64];
    __shared__ unsigned wds[2][2][64];
    __shared__ float mrg[4 * NT * 128];
    __shared__ float Zbuf[64];

    int tid = threadIdx.x, w = tid >> 5, lane = tid & 31;
    int rg = w >> 1, kg = w & 1;
    int g = lane >> 2, t4 = lane & 3;
    int r0 = rg * 16 + g, r1 = r0 + 8;
    int gr0 = n0 + r0, gr1 = n0 + r1;

    uint32_t whs0 = (uint32_t)__cvta_generic_to_shared(&Whs[0][0]);

    float f10 = 0.f, ea0 = 0.f, eb0 = 0.f, f11 = 0.f, ea1 = 0.f, eb1 = 0.f;
    if (gr0 < NN) { f10 = f1v[(size_t)z*NN+gr0]; ea0 = eav[(size_t)z*NN+gr0]; eb0 = ebv[(size_t)z*NN+gr0]; }
    if (gr1 < NN) { f11 = f1v[(size_t)z*NN+gr1]; ea1 = eav[(size_t)z*NN+gr1]; eb1 = ebv[(size_t)z*NN+gr1]; }

    float acc[NT][4];
#pragma unroll
    for (int i = 0; i < NT; i++)
#pragma unroll
        for (int j = 0; j < 4; j++) acc[i][j] = 0.f;
    float zp0 = 0.f, zp1 = 0.f;

    auto build = [&](int mt, int buf) {
#pragma unroll
        for (int i = 0; i < (32 * CPR) / 256; i++) {
            int c = tid + i * 256;
            int row = c / CPR;
            int col = (c % CPR) * 4;
            uint32_t dst = whs0 + (uint32_t)(buf * 32 * BSTRIDE + row * BSTRIDE + col) * 4u;
            cp_async16(dst, wbb + (size_t)(mt * 32 + row) * O + col);
        }
        if (tid < 64) {
            int m = mt * 64 + tid;
            mfs[buf][tid] = (m < NN) ? mfb[m] : make_float4(0.f, 0.f, 0.f, 0.f);
        } else if (tid < 192) {
            int j = (tid - 64) >> 6, n = (tid - 64) & 63;
            int rr = n0 + n;
            int wi = mt * 2 + j;
            wds[buf][j][n] = (rr < NN && wi < WPR) ? bb[(size_t)wi * NN + rr] : 0u;
        }
    };

    build(0, 0);
    cp_async_commit();
    cp_async_wait0();
    __syncthreads();

    int kb = kg * 16;
    for (int mt = 0; mt < NT64; mt++) {
        int cur = mt & 1;
        if (mt + 1 < NT64) { build(mt + 1, cur ^ 1); cp_async_commit(); }
#pragma unroll
        for (int sub = 0; sub < 2; sub++) {
            unsigned w0 = wds[cur][sub][r0], w1 = wds[cur][sub][r1];
            int base = sub * 32 + kb;
            float4 qa = mfs[cur][base + 2 * t4];
            float4 qb = mfs[cur][base + 2 * t4 + 1];
            float4 qc = mfs[cur][base + 2 * t4 + 8];
            float4 qd = mfs[cur][base + 2 * t4 + 9];
            float w0a = attw_f(w0, kb + 2 * t4,     f10, ea0, eb0, qa);
            float w0b = attw_f(w0, kb + 2 * t4 + 1, f10, ea0, eb0, qb);
            float w0c = attw_f(w0, kb + 2 * t4 + 8, f10, ea0, eb0, qc);
            float w0d = attw_f(w0, kb + 2 * t4 + 9, f10, ea0, eb0, qd);
            float w1a = attw_f(w1, kb + 2 * t4,     f11, ea1, eb1, qa);
            float w1b = attw_f(w1, kb + 2 * t4 + 1, f11, ea1, eb1, qb);
            float w1c = attw_f(w1, kb + 2 * t4 + 8, f11, ea1, eb1, qc);
            float w1d = attw_f(w1, kb + 2 * t4 + 9, f11, ea1, eb1, qd);
            zp0 += (w0a + w0b) + (w0c + w0d);
            zp1 += (w1a + w1b) + (w1c + w1d);
            uint32_t a0 = pack_bf16x2(w0b, w0a);
            uint32_t a1 = pack_bf16x2(w1b, w1a);
            uint32_t a2 = pack_bf16x2(w0d, w0c);
            uint32_t a3 = pack_bf16x2(w1d, w1c);
            int row0 = sub * 16 + kg * 8 + t4, row1 = row0 + 4;
#pragma unroll
            for (int nt = 0; nt < NT; nt++) {
                int col = nt * 8 + g;
                uint32_t b0 = Whs[cur][row0 * BSTRIDE + col];
                uint32_t b1 = Whs[cur][row1 * BSTRIDE + col];
                mma_bf16(acc[nt], a0, a1, a2, a3, b0, b1);
            }
        }
        cp_async_wait0();
        __syncthreads();
    }

#pragma unroll
    for (int d = 1; d < 4; d <<= 1) {
        zp0 += __shfl_xor_sync(0xffffffffu, zp0, d);
        zp1 += __shfl_xor_sync(0xffffffffu, zp1, d);
    }

    int flat = rg * 32 + lane;
    if (kg == 1) {
#pragma unroll
        for (int nt = 0; nt < NT; nt++)
#pragma unroll
            for (int j = 0; j < 4; j++)
                mrg[(nt * 4 + j) * 128 + flat] = acc[nt][j];
        if (t4 == 0) { Zbuf[r0] = zp0; Zbuf[r1] = zp1; }
    }
    __syncthreads();
    if (kg == 0) {
#pragma unroll
        for (int nt = 0; nt < NT; nt++)
#pragma unroll
            for (int j = 0; j < 4; j++)
                acc[nt][j] += mrg[(nt * 4 + j) * 128 + flat];
        zp0 += Zbuf[r0];
        zp1 += Zbuf[r1];
        float inv0 = (zp0 > 0.f) ? 1.f / zp0 : 0.f;
        float inv1 = (zp1 > 0.f) ? 1.f / zp1 : 0.f;
#pragma unroll
        for (int nt = 0; nt < NT; nt++) {
            int col = nt * 8 + 2 * t4;
            if (gr0 < NN) {
                float v0 = acc[nt][0] * inv0;
                float v1 = acc[nt][1] * inv0;
                v0 = v0 > 0.f ? v0 : (expf(v0) - 1.f);
                v1 = v1 > 0.f ? v1 : (expf(v1) - 1.f);
                *(float2*)&outp[(size_t)gr0 * LDW + (a * HHD + h) * O + col] = make_float2(v0, v1);
            }
            if (gr1 < NN) {
                float v2 = acc[nt][2] * inv1;
                float v3 = acc[nt][3] * inv1;
                v2 = v2 > 0.f ? v2 : (expf(v2) - 1.f);
                v3 = v3 > 0.f ? v3 : (expf(v3) - 1.f);
                *(float2*)&outp[(size_t)gr1 * LDW + (a * HHD + h) * O + col] = make_float2(v2, v3);
            }
        }
    }
}

// ---------------- fused interproj2 + fusion2 + log_softmax ----------------
__global__ void ipfus2_kernel(const float* __restrict__ gat2,
                              const float* __restrict__ wint2,
                              const float* __restrict__ bint2,
                              const float* __restrict__ wfus2,
                              const float* __restrict__ bfus2,
                              float* __restrict__ out, int out_size) {
    __shared__ float w2s[HO2D][9];
    __shared__ float wf2s[16][9];
    __shared__ float b2s[8], bf2s[8];
    __shared__ float h2ps[64][17];
    __shared__ float lg[64][9];

    int tid = threadIdx.x;
#pragma unroll
    for (int i = 0; i < 4; i++) {
        int e = tid + i * 256;
        if (e < HO2D * NCLSD) {
            int k = e & 127, c = e >> 7;
            w2s[k][c] = wint2[c * HO2D + k];
        }
    }
    if (tid < 16 * NCLSD) {
        int ee = tid & 15, c = tid >> 4;
        wf2s[ee][c] = wfus2[c * (AA * NCLSD) + ee];
    }
    if (tid < 8) { b2s[tid] = bint2[tid]; bf2s[tid] = bfus2[tid]; }
    __syncthreads();

    int r = tid >> 2, t4 = tid & 3;
    int row = blockIdx.x * 64 + r;
    int a = t4 >> 1, cb = (t4 & 1) * 4;
    if (row < NN) {
        float acc[4] = {0.f, 0.f, 0.f, 0.f};
        const float* gr = gat2 + (size_t)row * LDW2 + a * HO2D;
        for (int k = 0; k < HO2D; k += 4) {
            float4 gv = *(const float4*)(gr + k);
#pragma unroll
            for (int j = 0; j < 4; j++) {
                acc[j] += gv.x * w2s[k][cb + j] + gv.y * w2s[k + 1][cb + j]
                        + gv.z * w2s[k + 2][cb + j] + gv.w * w2s[k + 3][cb + j];
            }
        }
#pragma unroll
        for (int j = 0; j < 4; j++) {
            float v = acc[j] + b2s[cb + j];
            v = v > 0.f ? v : (expf(v) - 1.f);
            h2ps[r][t4 * 4 + j] = v;
        }
    }
    __syncwarp();
    if (row < NN) {
#pragma unroll
        for (int ci = 0; ci < 2; ci++) {
            int c = t4 * 2 + ci;
            float lv = bf2s[c];
#pragma unroll
            for (int e = 0; e < 16; e++) lv += h2ps[r][e] * wf2s[e][c];
            lg[r][c] = lv;
        }
    }
    __syncwarp();
    if (row < NN && t4 == 0) {
        float mx = -1e30f;
#pragma unroll
        for (int c = 0; c < 8; c++) mx = fmaxf(mx, lg[r][c]);
        float s = 0.f;
#pragma unroll
        for (int c = 0; c < 8; c++) s += expf(lg[r][c] - mx);
        float l = logf(s) + mx;
#pragma unroll
        for (int c = 0; c < 8; c++) {
            int idx = row * NCLSD + c;
            if (idx < out_size) out[idx] = lg[r][c] - l;
        }
    }
}

// ---------------- L1 scalar ----------------
__global__ void l1_kernel(const float* __restrict__ wfus1, const float* __restrict__ wfus2,
                          float* __restrict__ out, int out_size) {
    __shared__ float red[256];
    int tid = threadIdx.x;
    float s1 = 0.f, s2 = 0.f;
    for (int i = tid; i < FUSD * AA * FUSD; i += 256) s1 += fabsf(wfus1[i]);
    for (int i = tid; i < NCLSD * AA * NCLSD; i += 256) s2 += fabsf(wfus2[i]);
    red[tid] = s1 / (float)(FUSD * AA * FUSD) + s2 / (float)(NCLSD * AA * NCLSD);
    __syncthreads();
    for (int o = 128; o > 0; o >>= 1) {
        if (tid < o) red[tid] += red[tid + o];
        __syncthreads();
    }
    if (tid == 0 && out_size > NN * NCLSD) out[NN * NCLSD] = red[0];
}

// ---------------- host launcher ----------------
extern "C" void kernel_launch(void* const* d_in, const int* in_sizes, int n_in,
                              void* d_out, int out_size) {
    const float* x     = (const float*)d_in[0];
    const int*   adj   = (const int*)d_in[1];
    const float* W1    = (const float*)d_in[2];
    const float* a1    = (const float*)d_in[3];
    const float* W2    = (const float*)d_in[4];
    const float* a2    = (const float*)d_in[5];
    const float* wint1 = (const float*)d_in[6];
    const float* bint1 = (const float*)d_in[7];
    const float* wfus1 = (const float*)d_in[8];
    const float* bfus1 = (const float*)d_in[9];
    const float* wint2 = (const float*)d_in[10];
    const float* bint2 = (const float*)d_in[11];
    const float* wfus2 = (const float*)d_in[12];
    const float* bfus2 = (const float*)d_in[13];
    float* out = (float*)d_out;

    float *pgat1, *pgat2;
    float *pf1, *pea, *peb;
    float4* pmfac;
    uint32_t* pWhB;
    float *ph1p, *pout1;
    unsigned* pbits;
    cudaGetSymbolAddress((void**)&pgat1, g_gat1);
    cudaGetSymbolAddress((void**)&pgat2, g_gat2);
    cudaGetSymbolAddress((void**)&pf1, g_f1);
    cudaGetSymbolAddress((void**)&pea, g_ea);
    cudaGetSymbolAddress((void**)&peb, g_eb);
    cudaGetSymbolAddress((void**)&pmfac, g_mfac4);
    cudaGetSymbolAddress((void**)&pWhB, g_WhB);
    cudaGetSymbolAddress((void**)&pbits, g_bits);
    cudaGetSymbolAddress((void**)&ph1p, g_h1p);
    cudaGetSymbolAddress((void**)&pout1, g_out1);

    int nblk64 = (NN + 63) / 64;     // 47
    int nblk32 = (NN + 31) / 32;     // 94

    // adjacency bitmask
    {
        long long warps = (long long)AA * NN * WPR;
        int blocks = (int)((warps * 32 + 255) / 256);
        bitmask_kernel<<<blocks, 256>>>(adj);
    }

    // stage 1: Wh1 bf16 GEMM with fused fprep + bf16 repack
    gemm_whprep_kernel<O1D><<<dim3(nblk64, AA * HHD), 256>>>(
        x, W1, a1, pWhB, pf1, pea, peb, pmfac,
        NN, NFEATD, NFEATD, O1D, (long long)NFEATD * O1D);

    // att1
    att_mma_kernel<O1D><<<dim3(nblk64, AA * HHD), 256>>>(
        pWhB, pf1, pea, peb, pmfac, pbits, pgat1);

    // interproj1: elu(gat1[:, a*256:(a+1)*256] @ wint1^T + bint1) -> h1p[n][a*64+g]
    gemm_bt_kernel<<<dim3(nblk32, AA), 256>>>(
        pgat1, wint1, ph1p, bint1, NN, HO1D, LDW1, HO1D, AA * FUSD, FUSD, 1);

    // fusion1: out1 = h1p @ wfus1^T + bfus1
    gemm_bt_kernel<<<dim3(nblk32, 1), 256>>>(
        ph1p, wfus1, pout1, bfus1, NN, AA * FUSD, AA * FUSD, 0, FUSD, 0, 0);

    // stage 2: Wh2 bf16 GEMM with fused fprep + repack
    gemm_whprep_kernel<O2D><<<dim3(nblk64, AA * HHD), 256>>>(
        pout1, W2, a2, pWhB, pf1, pea, peb, pmfac,
        NN, FUSD, FUSD, O2D, (long long)FUSD * O2D);

    att_mma_kernel<O2D><<<dim3(nblk64, AA * HHD), 256>>>(
        pWhB, pf1, pea, peb, pmfac, pbits, pgat2);

    // fused interproj2 + fusion2 + log_softmax -> out
    ipfus2_kernel<<<nblk64, 256>>>(pgat2, wint2, bint2, wfus2, bfus2, out, out_size);

    l1_kernel<<<1, 256>>>(wfus1, wfus2, out, out_size);
}